// round 14
// baseline (speedup 1.0000x reference)
#include <cuda_runtime.h>
#include <cuda_bf16.h>
#include <cstdint>

// Problem constants
#define BB  16
#define TT  12
#define NN  1024
#define DD  512
#define HH  8
#define HD  64
#define CC  128
#define BTT (BB*TT)          // 192
#define MQ  (BTT*NN)         // 196608
#define MKV (BTT*CC)         // 24576

// ---------------- device scratch (no allocations allowed) ----------------
__device__ float g_q [(size_t)MQ  * DD];   // scaled q (fp32)
__device__ float g_ao[(size_t)MQ  * DD];   // attention output (fp32)
__device__ float g_xp[(size_t)MKV * DD];   // pooled x
__device__ float g_k [(size_t)MKV * DD];   // pooled k
__device__ float g_v [(size_t)MKV * DD];   // pooled v

// ---------------- helpers ----------------
__device__ __forceinline__ unsigned smem_u32(const void* p) {
    return (unsigned)__cvta_generic_to_shared(p);
}

// split two floats into packed bf16 hi pair + bf16 lo pair (residual)
__device__ __forceinline__ void split_pack(float x0, float x1, unsigned& hi, unsigned& lo) {
    __nv_bfloat162 h2 = __floats2bfloat162_rn(x0, x1);
    float r0 = x0 - __bfloat162float(h2.x);
    float r1 = x1 - __bfloat162float(h2.y);
    __nv_bfloat162 l2 = __floats2bfloat162_rn(r0, r1);
    hi = *reinterpret_cast<unsigned*>(&h2);
    lo = *reinterpret_cast<unsigned*>(&l2);
}

__device__ __forceinline__ void split1(float x, unsigned short& h, unsigned short& l) {
    __nv_bfloat16 bh = __float2bfloat16(x);
    float r = x - __bfloat162float(bh);
    __nv_bfloat16 bl = __float2bfloat16(r);
    h = *reinterpret_cast<unsigned short*>(&bh);
    l = *reinterpret_cast<unsigned short*>(&bl);
}

__device__ __forceinline__ void ldm_x4(unsigned& r0, unsigned& r1, unsigned& r2, unsigned& r3, unsigned addr) {
    asm volatile("ldmatrix.sync.aligned.m8n8.x4.shared.b16 {%0,%1,%2,%3}, [%4];"
                 : "=r"(r0), "=r"(r1), "=r"(r2), "=r"(r3) : "r"(addr));
}
__device__ __forceinline__ void ldm_x2(unsigned& r0, unsigned& r1, unsigned addr) {
    asm volatile("ldmatrix.sync.aligned.m8n8.x2.shared.b16 {%0,%1}, [%2];"
                 : "=r"(r0), "=r"(r1) : "r"(addr));
}
__device__ __forceinline__ void mma_acc(float* c, const unsigned* a, unsigned b0, unsigned b1) {
    asm volatile("mma.sync.aligned.m16n8k16.row.col.f32.bf16.bf16.f32 "
                 "{%0,%1,%2,%3}, {%4,%5,%6,%7}, {%8,%9}, {%0,%1,%2,%3};"
                 : "+f"(c[0]), "+f"(c[1]), "+f"(c[2]), "+f"(c[3])
                 : "r"(a[0]), "r"(a[1]), "r"(a[2]), "r"(a[3]), "r"(b0), "r"(b1));
}

// ---------------- pooling: xp[bt,c,d] = mean_j x[bt, c*8+j, d] ----------------
__global__ void pool_kernel(const float* __restrict__ x, float* __restrict__ xp) {
    int idx = blockIdx.x * blockDim.x + threadIdx.x;   // over MKV*DD/4 float4s
    if (idx >= MKV * DD / 4) return;
    int d4  = idx & (DD / 4 - 1);     // 0..127
    int btc = idx >> 7;
    int bt  = btc / CC, c = btc % CC;
    const float4* base = (const float4*)x;
    float4 s = make_float4(0.f, 0.f, 0.f, 0.f);
#pragma unroll
    for (int j = 0; j < 8; j++) {
        float4 v = base[(size_t)(bt * NN + c * 8 + j) * (DD / 4) + d4];
        s.x += v.x; s.y += v.y; s.z += v.z; s.w += v.w;
    }
    s.x *= 0.125f; s.y *= 0.125f; s.z *= 0.125f; s.w *= 0.125f;
    ((float4*)xp)[idx] = s;
}

// ---------------- split-bf16 GEMM: C[M,512] = (A[M,512] @ W[512,512] + bias) * scale ----------------
#define BK   32
#define APAD 8
#define ASTR (BK + APAD)   // 40 bf16 -> 80B row stride, conflict-free ldmatrix

__global__ __launch_bounds__(256, 2)
void gemm_split(const float* __restrict__ A, const float* __restrict__ W,
                const float* __restrict__ bias, float* __restrict__ Cout, float scale) {
    __shared__ unsigned short sAh[128][ASTR], sAl[128][ASTR];
    __shared__ unsigned short sBh[128][ASTR], sBl[128][ASTR];  // W transposed: [n][k]

    const int tid  = threadIdx.x;
    const int lane = tid & 31, warp = tid >> 5;
    const int wm = warp >> 1, wn = warp & 1;       // 4 x 2 warp grid, warp tile 32x64
    const int m0 = blockIdx.y * 128;
    const int n0 = blockIdx.x * 128;

    float acc[2][8][4];
#pragma unroll
    for (int i = 0; i < 2; i++)
#pragma unroll
        for (int j = 0; j < 8; j++) { acc[i][j][0] = 0.f; acc[i][j][1] = 0.f; acc[i][j][2] = 0.f; acc[i][j][3] = 0.f; }

    const int ar  = tid >> 3, ac4 = tid & 7;       // A: 32 rows/pass, 8 float4 per row
    const int wkk = tid >> 5, wc4 = tid & 31;      // W: 8 k-rows/pass, 32 float4 per row

    for (int k0 = 0; k0 < DD; k0 += BK) {
        // load + split A tile [128 x 32]
#pragma unroll
        for (int p = 0; p < 4; p++) {
            int r = ar + p * 32;
            float4 v = *(const float4*)&A[(size_t)(m0 + r) * DD + k0 + ac4 * 4];
            unsigned h01, l01, h23, l23;
            split_pack(v.x, v.y, h01, l01);
            split_pack(v.z, v.w, h23, l23);
            *(uint2*)&sAh[r][ac4 * 4] = make_uint2(h01, h23);
            *(uint2*)&sAl[r][ac4 * 4] = make_uint2(l01, l23);
        }
        // load + split + transpose W tile [32 x 128] -> [n][k]
#pragma unroll
        for (int p = 0; p < 4; p++) {
            int kk = wkk + p * 8;
            float4 v = *(const float4*)&W[(size_t)(k0 + kk) * DD + n0 + wc4 * 4];
            unsigned short h, l;
            split1(v.x, h, l); sBh[wc4 * 4 + 0][kk] = h; sBl[wc4 * 4 + 0][kk] = l;
            split1(v.y, h, l); sBh[wc4 * 4 + 1][kk] = h; sBl[wc4 * 4 + 1][kk] = l;
            split1(v.z, h, l); sBh[wc4 * 4 + 2][kk] = h; sBl[wc4 * 4 + 2][kk] = l;
            split1(v.w, h, l); sBh[wc4 * 4 + 3][kk] = h; sBl[wc4 * 4 + 3][kk] = l;
        }
        __syncthreads();

#pragma unroll
        for (int ks = 0; ks < 2; ks++) {
            unsigned ah[2][4], al[2][4];
#pragma unroll
            for (int mt = 0; mt < 2; mt++) {
                int rr = wm * 32 + mt * 16 + (lane & 15);
                int cc = ks * 16 + (lane >> 4) * 8;
                ldm_x4(ah[mt][0], ah[mt][1], ah[mt][2], ah[mt][3], smem_u32(&sAh[rr][cc]));
                ldm_x4(al[mt][0], al[mt][1], al[mt][2], al[mt][3], smem_u32(&sAl[rr][cc]));
            }
#pragma unroll
            for (int nt = 0; nt < 8; nt++) {
                int rr = wn * 64 + nt * 8 + (lane & 7);
                int cc = ks * 16 + ((lane >> 3) & 1) * 8;
                unsigned bh0, bh1, bl0, bl1;
                ldm_x2(bh0, bh1, smem_u32(&sBh[rr][cc]));
                ldm_x2(bl0, bl1, smem_u32(&sBl[rr][cc]));
#pragma unroll
                for (int mt = 0; mt < 2; mt++) {
                    mma_acc(acc[mt][nt], ah[mt], bh0, bh1);   // hi*hi
                    mma_acc(acc[mt][nt], ah[mt], bl0, bl1);   // hi*lo
                    mma_acc(acc[mt][nt], al[mt], bh0, bh1);   // lo*hi
                }
            }
        }
        __syncthreads();
    }

    // epilogue: (+bias)*scale, fp32 out
#pragma unroll
    for (int mt = 0; mt < 2; mt++) {
        int row = m0 + wm * 32 + mt * 16 + (lane >> 2);
#pragma unroll
        for (int nt = 0; nt < 8; nt++) {
            int col = n0 + wn * 64 + nt * 8 + (lane & 3) * 2;
            float b0 = bias[col], b1 = bias[col + 1];
            float2 v0 = make_float2((acc[mt][nt][0] + b0) * scale, (acc[mt][nt][1] + b1) * scale);
            float2 v1 = make_float2((acc[mt][nt][2] + b0) * scale, (acc[mt][nt][3] + b1) * scale);
            *(float2*)&Cout[(size_t)row * DD + col]       = v0;
            *(float2*)&Cout[(size_t)(row + 8) * DD + col] = v1;
        }
    }
}

// ---------------- fused attention ----------------
// grid: (N/128, H, BT); block 256 threads (8 warps, 16 q-rows per warp)
#define QPAD 8
#define QSTR (HD + QPAD)   // 72
#define VSTR (CC + QPAD)   // 136
#define ATTN_SMEM ((4 * 128 * QSTR + 2 * 64 * VSTR) * 2)   // 108544 bytes

__global__ __launch_bounds__(256)
void attn_kernel(const float* __restrict__ q, const float* __restrict__ k,
                 const float* __restrict__ v, const float* __restrict__ adp,
                 float* __restrict__ out) {
    extern __shared__ unsigned short sm[];
    unsigned short* p = sm;
    unsigned short (*sQh)[QSTR] = (unsigned short(*)[QSTR])p; p += 128 * QSTR;
    unsigned short (*sQl)[QSTR] = (unsigned short(*)[QSTR])p; p += 128 * QSTR;
    unsigned short (*sKh)[QSTR] = (unsigned short(*)[QSTR])p; p += 128 * QSTR;
    unsigned short (*sKl)[QSTR] = (unsigned short(*)[QSTR])p; p += 128 * QSTR;
    unsigned short (*sVh)[VSTR] = (unsigned short(*)[VSTR])p; p += 64 * VSTR;   // V transposed [d][c]
    unsigned short (*sVl)[VSTR] = (unsigned short(*)[VSTR])p;

    const int tid = threadIdx.x, lane = tid & 31, warp = tid >> 5;
    const int n0 = blockIdx.x * 128;
    const int h  = blockIdx.y;
    const int bt = blockIdx.z;

    const int lr = tid >> 4, lc4 = tid & 15;   // 16 rows/pass, 16 float4 per row
#pragma unroll
    for (int pp = 0; pp < 8; pp++) {
        int r = lr + pp * 16;
        // Q (already pre-scaled by 1/sqrt(HD))
        float4 vq = *(const float4*)&q[(size_t)(bt * NN + n0 + r) * DD + h * HD + lc4 * 4];
        unsigned h01, l01, h23, l23;
        split_pack(vq.x, vq.y, h01, l01); split_pack(vq.z, vq.w, h23, l23);
        *(uint2*)&sQh[r][lc4 * 4] = make_uint2(h01, h23);
        *(uint2*)&sQl[r][lc4 * 4] = make_uint2(l01, l23);
        // K
        size_t koff = (size_t)(bt * CC + r) * DD + h * HD + lc4 * 4;
        float4 vk = *(const float4*)&k[koff];
        split_pack(vk.x, vk.y, h01, l01); split_pack(vk.z, vk.w, h23, l23);
        *(uint2*)&sKh[r][lc4 * 4] = make_uint2(h01, h23);
        *(uint2*)&sKl[r][lc4 * 4] = make_uint2(l01, l23);
        // V transposed
        float4 vv = *(const float4*)&v[koff];
        unsigned short hh, ll;
        split1(vv.x, hh, ll); sVh[lc4 * 4 + 0][r] = hh; sVl[lc4 * 4 + 0][r] = ll;
        split1(vv.y, hh, ll); sVh[lc4 * 4 + 1][r] = hh; sVl[lc4 * 4 + 1][r] = ll;
        split1(vv.z, hh, ll); sVh[lc4 * 4 + 2][r] = hh; sVl[lc4 * 4 + 2][r] = ll;
        split1(vv.w, hh, ll); sVh[lc4 * 4 + 3][r] = hh; sVl[lc4 * 4 + 3][r] = ll;
    }
    __syncthreads();

    // S = Q*K^T : warp owns rows [warp*16, warp*16+16), all 128 cols
    float S[16][4];
#pragma unroll
    for (int nt = 0; nt < 16; nt++) { S[nt][0] = 0.f; S[nt][1] = 0.f; S[nt][2] = 0.f; S[nt][3] = 0.f; }

#pragma unroll
    for (int ks = 0; ks < 4; ks++) {
        unsigned ah[4], al[4];
        {
            int rr = warp * 16 + (lane & 15);
            int cc = ks * 16 + (lane >> 4) * 8;
            ldm_x4(ah[0], ah[1], ah[2], ah[3], smem_u32(&sQh[rr][cc]));
            ldm_x4(al[0], al[1], al[2], al[3], smem_u32(&sQl[rr][cc]));
        }
#pragma unroll
        for (int nt = 0; nt < 16; nt++) {
            int rr = nt * 8 + (lane & 7);
            int cc = ks * 16 + ((lane >> 3) & 1) * 8;
            unsigned bh0, bh1, bl0, bl1;
            ldm_x2(bh0, bh1, smem_u32(&sKh[rr][cc]));
            ldm_x2(bl0, bl1, smem_u32(&sKl[rr][cc]));
            mma_acc(S[nt], ah, bh0, bh1);
            mma_acc(S[nt], ah, bl0, bl1);
            mma_acc(S[nt], al, bh0, bh1);
        }
    }

    // bias + softmax (rows g and g+8; quad = lanes sharing a row)
    const int g = lane >> 2, tq = lane & 3;
    const int rowg = n0 + warp * 16 + g;
    float mx0 = -1e30f, mx1 = -1e30f;
#pragma unroll
    for (int nt = 0; nt < 16; nt++) {
        float2 b0 = __ldg((const float2*)&adp[(size_t)rowg * CC + nt * 8 + tq * 2]);
        float2 b1 = __ldg((const float2*)&adp[(size_t)(rowg + 8) * CC + nt * 8 + tq * 2]);
        S[nt][0] += b0.x; S[nt][1] += b0.y; S[nt][2] += b1.x; S[nt][3] += b1.y;
        mx0 = fmaxf(mx0, fmaxf(S[nt][0], S[nt][1]));
        mx1 = fmaxf(mx1, fmaxf(S[nt][2], S[nt][3]));
    }
    mx0 = fmaxf(mx0, __shfl_xor_sync(0xffffffffu, mx0, 1));
    mx0 = fmaxf(mx0, __shfl_xor_sync(0xffffffffu, mx0, 2));
    mx1 = fmaxf(mx1, __shfl_xor_sync(0xffffffffu, mx1, 1));
    mx1 = fmaxf(mx1, __shfl_xor_sync(0xffffffffu, mx1, 2));
    float sum0 = 0.f, sum1 = 0.f;
#pragma unroll
    for (int nt = 0; nt < 16; nt++) {
        S[nt][0] = __expf(S[nt][0] - mx0); sum0 += S[nt][0];
        S[nt][1] = __expf(S[nt][1] - mx0); sum0 += S[nt][1];
        S[nt][2] = __expf(S[nt][2] - mx1); sum1 += S[nt][2];
        S[nt][3] = __expf(S[nt][3] - mx1); sum1 += S[nt][3];
    }
    sum0 += __shfl_xor_sync(0xffffffffu, sum0, 1);
    sum0 += __shfl_xor_sync(0xffffffffu, sum0, 2);
    sum1 += __shfl_xor_sync(0xffffffffu, sum1, 1);
    sum1 += __shfl_xor_sync(0xffffffffu, sum1, 2);
    float r0 = 1.f / sum0, r1 = 1.f / sum1;
#pragma unroll
    for (int nt = 0; nt < 16; nt++) {
        S[nt][0] *= r0; S[nt][1] *= r0; S[nt][2] *= r1; S[nt][3] *= r1;
    }

    // O = P * V   (P fragments built straight from S registers, hi/lo split)
    float O[8][4];
#pragma unroll
    for (int nt = 0; nt < 8; nt++) { O[nt][0] = 0.f; O[nt][1] = 0.f; O[nt][2] = 0.f; O[nt][3] = 0.f; }

#pragma unroll
    for (int ks = 0; ks < 8; ks++) {
        unsigned ph[4], pl[4];
        split_pack(S[2 * ks][0],     S[2 * ks][1],     ph[0], pl[0]);
        split_pack(S[2 * ks][2],     S[2 * ks][3],     ph[1], pl[1]);
        split_pack(S[2 * ks + 1][0], S[2 * ks + 1][1], ph[2], pl[2]);
        split_pack(S[2 * ks + 1][2], S[2 * ks + 1][3], ph[3], pl[3]);
#pragma unroll
        for (int nt = 0; nt < 8; nt++) {
            int rr = nt * 8 + (lane & 7);
            int cc = ks * 16 + ((lane >> 3) & 1) * 8;
            unsigned bh0, bh1, bl0, bl1;
            ldm_x2(bh0, bh1, smem_u32(&sVh[rr][cc]));
            ldm_x2(bl0, bl1, smem_u32(&sVl[rr][cc]));
            mma_acc(O[nt], ph, bh0, bh1);
            mma_acc(O[nt], ph, bl0, bl1);
            mma_acc(O[nt], pl, bh0, bh1);
        }
    }

    // write merged-head output
#pragma unroll
    for (int nt = 0; nt < 8; nt++) {
        int col = h * HD + nt * 8 + tq * 2;
        *(float2*)&out[(size_t)(bt * NN + rowg) * DD + col]     = make_float2(O[nt][0], O[nt][1]);
        *(float2*)&out[(size_t)(bt * NN + rowg + 8) * DD + col] = make_float2(O[nt][2], O[nt][3]);
    }
}

// ---------------- launch ----------------
extern "C" void kernel_launch(void* const* d_in, const int* in_sizes, int n_in,
                              void* d_out, int out_size) {
    const float* x   = (const float*)d_in[0];
    const float* Wq  = (const float*)d_in[1];
    const float* bq  = (const float*)d_in[2];
    const float* Wk  = (const float*)d_in[3];
    const float* bk  = (const float*)d_in[4];
    const float* Wv  = (const float*)d_in[5];
    const float* bv  = (const float*)d_in[6];
    const float* Wo  = (const float*)d_in[7];
    const float* bo  = (const float*)d_in[8];
    const float* adp = (const float*)d_in[9];
    float* out = (float*)d_out;

    float *qp, *aop, *xpp, *kp, *vp;
    cudaGetSymbolAddress((void**)&qp,  g_q);
    cudaGetSymbolAddress((void**)&aop, g_ao);
    cudaGetSymbolAddress((void**)&xpp, g_xp);
    cudaGetSymbolAddress((void**)&kp,  g_k);
    cudaGetSymbolAddress((void**)&vp,  g_v);

    cudaFuncSetAttribute(attn_kernel, cudaFuncAttributeMaxDynamicSharedMemorySize, ATTN_SMEM);

    // 1) pooled x (linearity: pool before k/v projections)
    pool_kernel<<<(MKV * DD / 4 + 255) / 256, 256>>>(x, xpp);
    // 2) q = (x@Wq + bq) / sqrt(HD)
    gemm_split<<<dim3(4, MQ / 128), 256>>>(x, Wq, bq, qp, 0.125f);
    // 3) k, v on pooled x
    gemm_split<<<dim3(4, MKV / 128), 256>>>(xpp, Wk, bk, kp, 1.0f);
    gemm_split<<<dim3(4, MKV / 128), 256>>>(xpp, Wv, bv, vp, 1.0f);
    // 4) fused attention
    attn_kernel<<<dim3(NN / 128, HH, BTT), 256, ATTN_SMEM>>>(qp, kp, vp, adp, aop);
    // 5) output projection
    gemm_split<<<dim3(4, MQ / 128), 256>>>(aop, Wo, bo, out, 1.0f);
}

// round 16
// speedup vs baseline: 1.6601x; 1.6601x over previous
#include <cuda_runtime.h>
#include <cuda_bf16.h>
#include <cstdint>

// Problem constants
#define BB  16
#define TT  12
#define NN  1024
#define DD  512
#define HH  8
#define HD  64
#define CC  128
#define BTT (BB*TT)          // 192
#define MQ  (BTT*NN)         // 196608
#define MKV (BTT*CC)         // 24576

// ---------------- device scratch (bf16 stored as unsigned short) ----------------
__device__ unsigned short g_xh [(size_t)MQ  * DD];
__device__ unsigned short g_xl [(size_t)MQ  * DD];
__device__ unsigned short g_qh [(size_t)MQ  * DD];
__device__ unsigned short g_ql [(size_t)MQ  * DD];
__device__ unsigned short g_aoh[(size_t)MQ  * DD];
__device__ unsigned short g_aol[(size_t)MQ  * DD];
__device__ unsigned short g_xph[(size_t)MKV * DD];
__device__ unsigned short g_xpl[(size_t)MKV * DD];
__device__ unsigned short g_kh [(size_t)MKV * DD];
__device__ unsigned short g_kl [(size_t)MKV * DD];
__device__ unsigned short g_vh [(size_t)MKV * DD];
__device__ unsigned short g_vl [(size_t)MKV * DD];
__device__ unsigned short g_wh [4][(size_t)DD * DD];   // transposed [n][k] splits
__device__ unsigned short g_wl [4][(size_t)DD * DD];

// ---------------- helpers ----------------
__device__ __forceinline__ unsigned smem_u32(const void* p) {
    return (unsigned)__cvta_generic_to_shared(p);
}
__device__ __forceinline__ void split_pack(float x0, float x1, unsigned& hi, unsigned& lo) {
    __nv_bfloat162 h2 = __floats2bfloat162_rn(x0, x1);
    float r0 = x0 - __bfloat162float(h2.x);
    float r1 = x1 - __bfloat162float(h2.y);
    __nv_bfloat162 l2 = __floats2bfloat162_rn(r0, r1);
    hi = *reinterpret_cast<unsigned*>(&h2);
    lo = *reinterpret_cast<unsigned*>(&l2);
}
__device__ __forceinline__ void split1(float x, unsigned short& h, unsigned short& l) {
    __nv_bfloat16 bh = __float2bfloat16(x);
    float r = x - __bfloat162float(bh);
    __nv_bfloat16 bl = __float2bfloat16(r);
    h = *reinterpret_cast<unsigned short*>(&bh);
    l = *reinterpret_cast<unsigned short*>(&bl);
}
__device__ __forceinline__ void ldm_x4(unsigned& r0, unsigned& r1, unsigned& r2, unsigned& r3, unsigned addr) {
    asm volatile("ldmatrix.sync.aligned.m8n8.x4.shared.b16 {%0,%1,%2,%3}, [%4];"
                 : "=r"(r0), "=r"(r1), "=r"(r2), "=r"(r3) : "r"(addr));
}
__device__ __forceinline__ void ldm_x2(unsigned& r0, unsigned& r1, unsigned addr) {
    asm volatile("ldmatrix.sync.aligned.m8n8.x2.shared.b16 {%0,%1}, [%2];"
                 : "=r"(r0), "=r"(r1) : "r"(addr));
}
__device__ __forceinline__ void mma_acc(float* c, const unsigned* a, unsigned b0, unsigned b1) {
    asm volatile("mma.sync.aligned.m16n8k16.row.col.f32.bf16.bf16.f32 "
                 "{%0,%1,%2,%3}, {%4,%5,%6,%7}, {%8,%9}, {%0,%1,%2,%3};"
                 : "+f"(c[0]), "+f"(c[1]), "+f"(c[2]), "+f"(c[3])
                 : "r"(a[0]), "r"(a[1]), "r"(a[2]), "r"(a[3]), "r"(b0), "r"(b1));
}
__device__ __forceinline__ void cp_async16(unsigned dst, const void* src) {
    asm volatile("cp.async.cg.shared.global [%0], [%1], 16;" :: "r"(dst), "l"(src));
}

// ---------------- pre-pass kernels ----------------
__global__ void pool_split_kernel(const float* __restrict__ x,
                                  unsigned short* __restrict__ xph,
                                  unsigned short* __restrict__ xpl) {
    int idx = blockIdx.x * blockDim.x + threadIdx.x;   // over MKV*DD/4
    if (idx >= MKV * DD / 4) return;
    int d4  = idx & (DD / 4 - 1);
    int btc = idx >> 7;
    int bt  = btc / CC, c = btc % CC;
    const float4* base = (const float4*)x;
    float4 s = make_float4(0.f, 0.f, 0.f, 0.f);
#pragma unroll
    for (int j = 0; j < 8; j++) {
        float4 v = base[(size_t)(bt * NN + c * 8 + j) * (DD / 4) + d4];
        s.x += v.x; s.y += v.y; s.z += v.z; s.w += v.w;
    }
    s.x *= 0.125f; s.y *= 0.125f; s.z *= 0.125f; s.w *= 0.125f;
    unsigned h01, l01, h23, l23;
    split_pack(s.x, s.y, h01, l01); split_pack(s.z, s.w, h23, l23);
    ((uint2*)xph)[idx] = make_uint2(h01, h23);
    ((uint2*)xpl)[idx] = make_uint2(l01, l23);
}

__global__ void split_x_kernel(const float* __restrict__ x,
                               unsigned short* __restrict__ xh,
                               unsigned short* __restrict__ xl) {
    int idx = blockIdx.x * blockDim.x + threadIdx.x;   // over MQ*DD/4
    float4 v = ((const float4*)x)[idx];
    unsigned h01, l01, h23, l23;
    split_pack(v.x, v.y, h01, l01); split_pack(v.z, v.w, h23, l23);
    ((uint2*)xh)[idx] = make_uint2(h01, h23);
    ((uint2*)xl)[idx] = make_uint2(l01, l23);
}

// transpose + split weight: W[k][n] (512x512) -> H/L [n][k]
__global__ void wsplit_kernel(const float* __restrict__ W,
                              unsigned short* __restrict__ Hm,
                              unsigned short* __restrict__ Lm) {
    int idx = blockIdx.x * blockDim.x + threadIdx.x;   // 512*512
    int k = idx >> 9, n = idx & 511;
    unsigned short h, l;
    split1(W[idx], h, l);
    Hm[(size_t)n * DD + k] = h;
    Lm[(size_t)n * DD + k] = l;
}

// ---------------- split-bf16 mma.sync GEMM ----------------
// C[M,512] = (Ah+Al)[M,512] @ (Bh+Bl)^T[n][k]  ~=  AhBh + AhBl + AlBh
// block tile 128x256, BK=32, 3-stage cp.async pipeline, warp tile 64x64 (2x4 warps)
#define BKK 32
#define BM 128
#define BN 256
#define NSTAGE 3
#define ASTR 40                       // 32 + 8 pad (bf16 elems) -> conflict-free
#define A_MAT (BM*ASTR)               // 5120 elems per A matrix
#define B_MAT (BN*ASTR)               // 10240 elems per B matrix
#define STAGE_ELEM (2*A_MAT + 2*B_MAT)   // 30720 elems = 61440 B
#define GEMM_SMEM (NSTAGE*STAGE_ELEM*2)  // 184320 B

__device__ __forceinline__ void load_tile(unsigned smb, int s, int k0,
    const unsigned short* __restrict__ Ah, const unsigned short* __restrict__ Al,
    const unsigned short* __restrict__ Bh, const unsigned short* __restrict__ Bl,
    int m0, int n0, int tid)
{
    unsigned st = smb + s * (STAGE_ELEM * 2);
    // A: 128 rows x 4 16B-chunks = 512 chunks per matrix
#pragma unroll
    for (int i = 0; i < 2; i++) {
        int c   = tid + i * 256;
        int row = c >> 2, cb = c & 3;
        unsigned d = st + (row * ASTR + cb * 8) * 2;
        size_t  g = (size_t)(m0 + row) * DD + k0 + cb * 8;
        cp_async16(d,             Ah + g);
        cp_async16(d + A_MAT * 2, Al + g);
    }
    // B: 256 rows x 4 chunks = 1024 chunks per matrix
#pragma unroll
    for (int i = 0; i < 4; i++) {
        int c   = tid + i * 256;
        int row = c >> 2, cb = c & 3;
        unsigned d = st + (2 * A_MAT + row * ASTR + cb * 8) * 2;
        size_t  g = (size_t)(n0 + row) * DD + k0 + cb * 8;
        cp_async16(d,             Bh + g);
        cp_async16(d + B_MAT * 2, Bl + g);
    }
}

__global__ __launch_bounds__(256, 1)
void tc_gemm(const unsigned short* __restrict__ Ah, const unsigned short* __restrict__ Al,
             const unsigned short* __restrict__ Bh, const unsigned short* __restrict__ Bl,
             const float* __restrict__ bias, float scale, int mode,
             float* __restrict__ Cf, unsigned short* __restrict__ Ch, unsigned short* __restrict__ Cl)
{
    extern __shared__ __align__(128) unsigned short smg[];
    const unsigned smb = smem_u32(smg);

    const int tid  = threadIdx.x;
    const int lane = tid & 31, warp = tid >> 5;
    const int wm = warp >> 2, wn = warp & 3;          // 2x4 warp grid, warp tile 64x64
    const int m0 = blockIdx.y * BM;
    const int n0 = blockIdx.x * BN;

    float acc[4][8][4];
#pragma unroll
    for (int i = 0; i < 4; i++)
#pragma unroll
        for (int j = 0; j < 8; j++) {
            acc[i][j][0] = 0.f; acc[i][j][1] = 0.f; acc[i][j][2] = 0.f; acc[i][j][3] = 0.f;
        }

    const int NT = DD / BKK;   // 16
    // prologue: fill 2 stages
    load_tile(smb, 0, 0, Ah, Al, Bh, Bl, m0, n0, tid);
    asm volatile("cp.async.commit_group;");
    load_tile(smb, 1, BKK, Ah, Al, Bh, Bl, m0, n0, tid);
    asm volatile("cp.async.commit_group;");

    int ls = 2;   // next stage slot to fill
    for (int kt = 0; kt < NT; kt++) {
        int s = kt % NSTAGE;
        if (kt + 2 < NT) {
            load_tile(smb, ls, (kt + 2) * BKK, Ah, Al, Bh, Bl, m0, n0, tid);
            ls = (ls + 1) % NSTAGE;
        }
        asm volatile("cp.async.commit_group;");   // may be empty near tail
        asm volatile("cp.async.wait_group 2;");
        __syncthreads();

        const unsigned st  = smb + s * (STAGE_ELEM * 2);
        const unsigned aH  = st;
        const unsigned aL  = st + A_MAT * 2;
        const unsigned bH  = st + 2 * A_MAT * 2;
        const unsigned bL  = st + (2 * A_MAT + B_MAT) * 2;

#pragma unroll
        for (int ks = 0; ks < 2; ks++) {
            unsigned ah[4][4], al[4][4], bh[8][2], bl[8][2];
            const int cc = ks * 16 + (lane >> 4) * 8;
#pragma unroll
            for (int mt = 0; mt < 4; mt++) {
                int rr = wm * 64 + mt * 16 + (lane & 15);
                unsigned off = (rr * ASTR + cc) * 2;
                ldm_x4(ah[mt][0], ah[mt][1], ah[mt][2], ah[mt][3], aH + off);
                ldm_x4(al[mt][0], al[mt][1], al[mt][2], al[mt][3], aL + off);
            }
#pragma unroll
            for (int nb = 0; nb < 4; nb++) {
                int rr = wn * 64 + nb * 16 + (lane & 15);
                unsigned off = (rr * ASTR + cc) * 2;
                unsigned r0, r1, r2, r3;
                ldm_x4(r0, r1, r2, r3, bH + off);
                bh[2*nb][0] = r0; bh[2*nb][1] = r2; bh[2*nb+1][0] = r1; bh[2*nb+1][1] = r3;
                ldm_x4(r0, r1, r2, r3, bL + off);
                bl[2*nb][0] = r0; bl[2*nb][1] = r2; bl[2*nb+1][0] = r1; bl[2*nb+1][1] = r3;
            }
#pragma unroll
            for (int mt = 0; mt < 4; mt++)
#pragma unroll
                for (int nt = 0; nt < 8; nt++) {
                    mma_acc(acc[mt][nt], ah[mt], bh[nt][0], bh[nt][1]);   // hi*hi
                    mma_acc(acc[mt][nt], ah[mt], bl[nt][0], bl[nt][1]);   // hi*lo
                    mma_acc(acc[mt][nt], al[mt], bh[nt][0], bh[nt][1]);   // lo*hi
                }
        }
        __syncthreads();
    }

    // epilogue: (+bias)*scale, direct register stores
#pragma unroll
    for (int mt = 0; mt < 4; mt++) {
        int row = m0 + wm * 64 + mt * 16 + (lane >> 2);
#pragma unroll
        for (int nt = 0; nt < 8; nt++) {
            int col = n0 + wn * 64 + nt * 8 + (lane & 3) * 2;
            float b0 = bias[col], b1 = bias[col + 1];
            float v0 = (acc[mt][nt][0] + b0) * scale;
            float v1 = (acc[mt][nt][1] + b1) * scale;
            float v2 = (acc[mt][nt][2] + b0) * scale;
            float v3 = (acc[mt][nt][3] + b1) * scale;
            size_t o0 = (size_t)row * DD + col;
            size_t o1 = (size_t)(row + 8) * DD + col;
            if (mode == 0) {
                *(float2*)&Cf[o0] = make_float2(v0, v1);
                *(float2*)&Cf[o1] = make_float2(v2, v3);
            } else {
                unsigned hA, lA, hB, lB;
                split_pack(v0, v1, hA, lA);
                split_pack(v2, v3, hB, lB);
                *(unsigned*)(Ch + o0) = hA; *(unsigned*)(Cl + o0) = lA;
                *(unsigned*)(Ch + o1) = hB; *(unsigned*)(Cl + o1) = lB;
            }
        }
    }
}

// ---------------- fused attention (bf16-split inputs/outputs) ----------------
#define QPAD 8
#define QSTR (HD + QPAD)   // 72
#define VSTR (CC + QPAD)   // 136
#define ATTN_SMEM ((4 * 128 * QSTR + 2 * 64 * VSTR) * 2)   // 108544 bytes

__global__ __launch_bounds__(256)
void attn_kernel(const unsigned short* __restrict__ qh, const unsigned short* __restrict__ ql,
                 const unsigned short* __restrict__ kh, const unsigned short* __restrict__ kl,
                 const unsigned short* __restrict__ vh, const unsigned short* __restrict__ vl,
                 const float* __restrict__ adp,
                 unsigned short* __restrict__ aoh, unsigned short* __restrict__ aol) {
    extern __shared__ unsigned short sm[];
    unsigned short* p = sm;
    unsigned short (*sQh)[QSTR] = (unsigned short(*)[QSTR])p; p += 128 * QSTR;
    unsigned short (*sQl)[QSTR] = (unsigned short(*)[QSTR])p; p += 128 * QSTR;
    unsigned short (*sKh)[QSTR] = (unsigned short(*)[QSTR])p; p += 128 * QSTR;
    unsigned short (*sKl)[QSTR] = (unsigned short(*)[QSTR])p; p += 128 * QSTR;
    unsigned short (*sVh)[VSTR] = (unsigned short(*)[VSTR])p; p += 64 * VSTR;   // V transposed [d][c]
    unsigned short (*sVl)[VSTR] = (unsigned short(*)[VSTR])p;

    const int tid = threadIdx.x, lane = tid & 31, warp = tid >> 5;
    const int n0 = blockIdx.x * 128;
    const int h  = blockIdx.y;
    const int bt = blockIdx.z;

    // loads: 2 threads per row, 32 bf16 cols each
    {
        const int lr = tid >> 1, half = tid & 1;
        size_t qoff = (size_t)(bt * NN + n0 + lr) * DD + h * HD + half * 32;
        size_t koff = (size_t)(bt * CC + lr) * DD + h * HD + half * 32;
#pragma unroll
        for (int j = 0; j < 4; j++) {
            *(uint4*)&sQh[lr][half * 32 + j * 8] = *(const uint4*)(qh + qoff + j * 8);
            *(uint4*)&sQl[lr][half * 32 + j * 8] = *(const uint4*)(ql + qoff + j * 8);
            *(uint4*)&sKh[lr][half * 32 + j * 8] = *(const uint4*)(kh + koff + j * 8);
            *(uint4*)&sKl[lr][half * 32 + j * 8] = *(const uint4*)(kl + koff + j * 8);
        }
#pragma unroll
        for (int j = 0; j < 4; j++) {
            uint4 th = *(const uint4*)(vh + koff + j * 8);
            uint4 tl = *(const uint4*)(vl + koff + j * 8);
            const unsigned short* ph_ = (const unsigned short*)&th;
            const unsigned short* pl_ = (const unsigned short*)&tl;
#pragma unroll
            for (int e = 0; e < 8; e++) {
                sVh[half * 32 + j * 8 + e][lr] = ph_[e];
                sVl[half * 32 + j * 8 + e][lr] = pl_[e];
            }
        }
    }
    __syncthreads();

    // S = Q*K^T
    float S[16][4];
#pragma unroll
    for (int nt = 0; nt < 16; nt++) { S[nt][0] = 0.f; S[nt][1] = 0.f; S[nt][2] = 0.f; S[nt][3] = 0.f; }

#pragma unroll
    for (int ks = 0; ks < 4; ks++) {
        unsigned ah[4], al[4];
        {
            int rr = warp * 16 + (lane & 15);
            int cc = ks * 16 + (lane >> 4) * 8;
            ldm_x4(ah[0], ah[1], ah[2], ah[3], smem_u32(&sQh[rr][cc]));
            ldm_x4(al[0], al[1], al[2], al[3], smem_u32(&sQl[rr][cc]));
        }
#pragma unroll
        for (int nt = 0; nt < 16; nt++) {
            int rr = nt * 8 + (lane & 7);
            int cc = ks * 16 + ((lane >> 3) & 1) * 8;
            unsigned bh0, bh1, bl0, bl1;
            ldm_x2(bh0, bh1, smem_u32(&sKh[rr][cc]));
            ldm_x2(bl0, bl1, smem_u32(&sKl[rr][cc]));
            mma_acc(S[nt], ah, bh0, bh1);
            mma_acc(S[nt], ah, bl0, bl1);
            mma_acc(S[nt], al, bh0, bh1);
        }
    }

    // bias + softmax
    const int g = lane >> 2, tq = lane & 3;
    const int rowg = n0 + warp * 16 + g;
    float mx0 = -1e30f, mx1 = -1e30f;
#pragma unroll
    for (int nt = 0; nt < 16; nt++) {
        float2 b0 = __ldg((const float2*)&adp[(size_t)rowg * CC + nt * 8 + tq * 2]);
        float2 b1 = __ldg((const float2*)&adp[(size_t)(rowg + 8) * CC + nt * 8 + tq * 2]);
        S[nt][0] += b0.x; S[nt][1] += b0.y; S[nt][2] += b1.x; S[nt][3] += b1.y;
        mx0 = fmaxf(mx0, fmaxf(S[nt][0], S[nt][1]));
        mx1 = fmaxf(mx1, fmaxf(S[nt][2], S[nt][3]));
    }
    mx0 = fmaxf(mx0, __shfl_xor_sync(0xffffffffu, mx0, 1));
    mx0 = fmaxf(mx0, __shfl_xor_sync(0xffffffffu, mx0, 2));
    mx1 = fmaxf(mx1, __shfl_xor_sync(0xffffffffu, mx1, 1));
    mx1 = fmaxf(mx1, __shfl_xor_sync(0xffffffffu, mx1, 2));
    float sum0 = 0.f, sum1 = 0.f;
#pragma unroll
    for (int nt = 0; nt < 16; nt++) {
        S[nt][0] = __expf(S[nt][0] - mx0); sum0 += S[nt][0];
        S[nt][1] = __expf(S[nt][1] - mx0); sum0 += S[nt][1];
        S[nt][2] = __expf(S[nt][2] - mx1); sum1 += S[nt][2];
        S[nt][3] = __expf(S[nt][3] - mx1); sum1 += S[nt][3];
    }
    sum0 += __shfl_xor_sync(0xffffffffu, sum0, 1);
    sum0 += __shfl_xor_sync(0xffffffffu, sum0, 2);
    sum1 += __shfl_xor_sync(0xffffffffu, sum1, 1);
    sum1 += __shfl_xor_sync(0xffffffffu, sum1, 2);
    float r0 = 1.f / sum0, r1 = 1.f / sum1;
#pragma unroll
    for (int nt = 0; nt < 16; nt++) {
        S[nt][0] *= r0; S[nt][1] *= r0; S[nt][2] *= r1; S[nt][3] *= r1;
    }

    // O = P * V
    float O[8][4];
#pragma unroll
    for (int nt = 0; nt < 8; nt++) { O[nt][0] = 0.f; O[nt][1] = 0.f; O[nt][2] = 0.f; O[nt][3] = 0.f; }

#pragma unroll
    for (int ks = 0; ks < 8; ks++) {
        unsigned ph[4], pl[4];
        split_pack(S[2 * ks][0],     S[2 * ks][1],     ph[0], pl[0]);
        split_pack(S[2 * ks][2],     S[2 * ks][3],     ph[1], pl[1]);
        split_pack(S[2 * ks + 1][0], S[2 * ks + 1][1], ph[2], pl[2]);
        split_pack(S[2 * ks + 1][2], S[2 * ks + 1][3], ph[3], pl[3]);
#pragma unroll
        for (int nt = 0; nt < 8; nt++) {
            int rr = nt * 8 + (lane & 7);
            int cc = ks * 16 + ((lane >> 3) & 1) * 8;
            unsigned bh0, bh1, bl0, bl1;
            ldm_x2(bh0, bh1, smem_u32(&sVh[rr][cc]));
            ldm_x2(bl0, bl1, smem_u32(&sVl[rr][cc]));
            mma_acc(O[nt], ph, bh0, bh1);
            mma_acc(O[nt], ph, bl0, bl1);
            mma_acc(O[nt], pl, bh0, bh1);
        }
    }

    // write merged-head output as split bf16
#pragma unroll
    for (int nt = 0; nt < 8; nt++) {
        int col = h * HD + nt * 8 + tq * 2;
        size_t o0 = (size_t)(bt * NN + rowg) * DD + col;
        size_t o1 = (size_t)(bt * NN + rowg + 8) * DD + col;
        unsigned hA, lA, hB, lB;
        split_pack(O[nt][0], O[nt][1], hA, lA);
        split_pack(O[nt][2], O[nt][3], hB, lB);
        *(unsigned*)(aoh + o0) = hA; *(unsigned*)(aol + o0) = lA;
        *(unsigned*)(aoh + o1) = hB; *(unsigned*)(aol + o1) = lB;
    }
}

// ---------------- launch ----------------
extern "C" void kernel_launch(void* const* d_in, const int* in_sizes, int n_in,
                              void* d_out, int out_size) {
    const float* x   = (const float*)d_in[0];
    const float* Wq  = (const float*)d_in[1];
    const float* bq  = (const float*)d_in[2];
    const float* Wk  = (const float*)d_in[3];
    const float* bk  = (const float*)d_in[4];
    const float* Wv  = (const float*)d_in[5];
    const float* bv  = (const float*)d_in[6];
    const float* Wo  = (const float*)d_in[7];
    const float* bo  = (const float*)d_in[8];
    const float* adp = (const float*)d_in[9];
    float* out = (float*)d_out;

    unsigned short *xh, *xl, *qh, *ql, *aoh, *aol, *xph, *xpl, *kh, *kl, *vh, *vl;
    unsigned short (*wh)[(size_t)DD * DD], (*wl)[(size_t)DD * DD];
    cudaGetSymbolAddress((void**)&xh,  g_xh);
    cudaGetSymbolAddress((void**)&xl,  g_xl);
    cudaGetSymbolAddress((void**)&qh,  g_qh);
    cudaGetSymbolAddress((void**)&ql,  g_ql);
    cudaGetSymbolAddress((void**)&aoh, g_aoh);
    cudaGetSymbolAddress((void**)&aol, g_aol);
    cudaGetSymbolAddress((void**)&xph, g_xph);
    cudaGetSymbolAddress((void**)&xpl, g_xpl);
    cudaGetSymbolAddress((void**)&kh,  g_kh);
    cudaGetSymbolAddress((void**)&kl,  g_kl);
    cudaGetSymbolAddress((void**)&vh,  g_vh);
    cudaGetSymbolAddress((void**)&vl,  g_vl);
    cudaGetSymbolAddress((void**)&wh,  g_wh);
    cudaGetSymbolAddress((void**)&wl,  g_wl);

    cudaFuncSetAttribute(tc_gemm, cudaFuncAttributeMaxDynamicSharedMemorySize, GEMM_SMEM);
    cudaFuncSetAttribute(attn_kernel, cudaFuncAttributeMaxDynamicSharedMemorySize, ATTN_SMEM);

    // pre-passes
    pool_split_kernel<<<(MKV * DD / 4 + 255) / 256, 256>>>(x, xph, xpl);
    split_x_kernel<<<MQ * DD / 4 / 256, 256>>>(x, xh, xl);
    wsplit_kernel<<<DD * DD / 256, 256>>>(Wq, wh[0], wl[0]);
    wsplit_kernel<<<DD * DD / 256, 256>>>(Wk, wh[1], wl[1]);
    wsplit_kernel<<<DD * DD / 256, 256>>>(Wv, wh[2], wl[2]);
    wsplit_kernel<<<DD * DD / 256, 256>>>(Wo, wh[3], wl[3]);

    // projections (mma.sync, pre-split operands)
    tc_gemm<<<dim3(DD / BN, MQ / BM),  256, GEMM_SMEM>>>(xh,  xl,  wh[0], wl[0], bq, 0.125f, 1, nullptr, qh, ql);
    tc_gemm<<<dim3(DD / BN, MKV / BM), 256, GEMM_SMEM>>>(xph, xpl, wh[1], wl[1], bk, 1.0f,   1, nullptr, kh, kl);
    tc_gemm<<<dim3(DD / BN, MKV / BM), 256, GEMM_SMEM>>>(xph, xpl, wh[2], wl[2], bv, 1.0f,   1, nullptr, vh, vl);

    // fused attention
    attn_kernel<<<dim3(NN / 128, HH, BTT), 256, ATTN_SMEM>>>(qh, ql, kh, kl, vh, vl, adp, aoh, aol);

    // output projection -> fp32 out
    tc_gemm<<<dim3(DD / BN, MQ / BM), 256, GEMM_SMEM>>>(aoh, aol, wh[3], wl[3], bo, 1.0f, 0, out, nullptr, nullptr);
}